// round 1
// baseline (speedup 1.0000x reference)
#include <cuda_runtime.h>
#include <math.h>

#define N_ELEM 131072
#define C_DIM  512
#define G_DIM  4096

// ---------------- scratch (no allocations allowed) ----------------
__device__ float g_fx[(size_t)N_ELEM * C_DIM];   // 256 MB
__device__ float g_eg[(size_t)N_ELEM * C_DIM];   // 256 MB
__device__ float g_denom[G_DIM * C_DIM];         // 8 MB
__device__ float g_y[G_DIM * C_DIM];             // 8 MB
__device__ float g_yh[G_DIM * C_DIM];            // 8 MB

// ---------------- zero accumulators (graph replays need this) ----------------
__global__ void zero_kernel() {
    int i = blockIdx.x * blockDim.x + threadIdx.x;   // over G*C/4 = 524288
    float4 z = make_float4(0.f, 0.f, 0.f, 0.f);
    ((float4*)g_denom)[i] = z;
    ((float4*)g_y)[i] = z;
}

// ---------------- fused dual GEMM: fx = xWf+bf ; eg = exp(xWg+bg), denom += eg ----------------
// 128x128x16 tile, 256 threads, 8x8 per thread.
// blockIdx.x in [0,8): 0-3 -> Wf half (cols 0..511), 4-7 -> Wg half.
__global__ __launch_bounds__(256, 2)
void fused_fg_kernel(const float* __restrict__ x, const int* __restrict__ ix,
                     const float* __restrict__ Wf, const float* __restrict__ bf,
                     const float* __restrict__ Wg, const float* __restrict__ bg)
{
    constexpr int BM = 128, BN = 128, BK = 16;
    __shared__ float As[BK][BM];
    __shared__ float Bs[BK][BN];
    __shared__ int   s_ix[BM];

    const int tid     = threadIdx.x;
    const int colTile = blockIdx.x;
    const bool isG    = (colTile >= 4);
    const float* __restrict__ W    = isG ? Wg : Wf;
    const float* __restrict__ bias = isG ? bg : bf;
    const int col0 = (colTile & 3) * BN;
    const int row0 = blockIdx.y * BM;

    if (tid < BM) s_ix[tid] = ix[row0 + tid];

    const int ty = tid >> 4, tx = tid & 15;
    const int trow = ty * 8, tcol = tx * 8;

    float acc[8][8];
#pragma unroll
    for (int i = 0; i < 8; i++)
#pragma unroll
        for (int j = 0; j < 8; j++) acc[i][j] = 0.f;

    for (int k0 = 0; k0 < C_DIM; k0 += BK) {
#pragma unroll
        for (int s = 0; s < 2; s++) {
            int l = tid + s * 256;
            // A tile: 128 rows x 16 k, transposed into As[k][row]
            int ar  = l >> 2;
            int akq = (l & 3) * 4;
            float4 av = *(const float4*)&x[(size_t)(row0 + ar) * C_DIM + k0 + akq];
            As[akq + 0][ar] = av.x;
            As[akq + 1][ar] = av.y;
            As[akq + 2][ar] = av.z;
            As[akq + 3][ar] = av.w;
            // B tile: 16 k-rows x 128 cols, row-major
            int bk  = l >> 5;
            int bcq = (l & 31) * 4;
            float4 bv = *(const float4*)&W[(size_t)(k0 + bk) * C_DIM + col0 + bcq];
            *(float4*)&Bs[bk][bcq] = bv;
        }
        __syncthreads();
#pragma unroll
        for (int k = 0; k < BK; k++) {
            float a[8], b[8];
#pragma unroll
            for (int i = 0; i < 8; i++) a[i] = As[k][trow + i];
#pragma unroll
            for (int j = 0; j < 8; j++) b[j] = Bs[k][tcol + j];
#pragma unroll
            for (int i = 0; i < 8; i++)
#pragma unroll
                for (int j = 0; j < 8; j++)
                    acc[i][j] = fmaf(a[i], b[j], acc[i][j]);
        }
        __syncthreads();
    }

    float bv[8];
#pragma unroll
    for (int j = 0; j < 8; j++) bv[j] = bias[col0 + tcol + j];

    if (!isG) {
#pragma unroll
        for (int i = 0; i < 8; i++) {
            size_t off = (size_t)(row0 + trow + i) * C_DIM + col0 + tcol;
            float4 v0 = make_float4(acc[i][0] + bv[0], acc[i][1] + bv[1],
                                    acc[i][2] + bv[2], acc[i][3] + bv[3]);
            float4 v1 = make_float4(acc[i][4] + bv[4], acc[i][5] + bv[5],
                                    acc[i][6] + bv[6], acc[i][7] + bv[7]);
            *(float4*)&g_fx[off]     = v0;
            *(float4*)&g_fx[off + 4] = v1;
        }
    } else {
#pragma unroll
        for (int i = 0; i < 8; i++) {
            int g = s_ix[trow + i];
            size_t off = (size_t)(row0 + trow + i) * C_DIM + col0 + tcol;
            float e[8];
#pragma unroll
            for (int j = 0; j < 8; j++) e[j] = expf(acc[i][j] + bv[j]);
            *(float4*)&g_eg[off]     = make_float4(e[0], e[1], e[2], e[3]);
            *(float4*)&g_eg[off + 4] = make_float4(e[4], e[5], e[6], e[7]);
            float* dptr = &g_denom[(size_t)g * C_DIM + col0 + tcol];
#pragma unroll
            for (int j = 0; j < 8; j++) atomicAdd(dptr + j, e[j]);
        }
    }
}

// ---------------- softmax-weighted aggregation: y[g] += fx * eg/denom[g] ----------------
__global__ void agg_kernel(const int* __restrict__ ix) {
    size_t idx = (size_t)blockIdx.x * blockDim.x + threadIdx.x;  // over N*C/4
    int n  = (int)(idx >> 7);          // C/4 = 128 vec4 per row
    int cq = (int)(idx & 127) << 2;
    int g  = ix[n];
    size_t eoff = ((size_t)n << 9) + cq;
    size_t doff = ((size_t)g << 9) + cq;
    float4 e = *(const float4*)&g_eg[eoff];
    float4 f = *(const float4*)&g_fx[eoff];
    float4 d = *(const float4*)&g_denom[doff];
    float* yp = &g_y[doff];
    atomicAdd(yp + 0, f.x * (e.x / d.x));
    atomicAdd(yp + 1, f.y * (e.y / d.y));
    atomicAdd(yp + 2, f.z * (e.z / d.z));
    atomicAdd(yp + 3, f.w * (e.w / d.w));
}

// ---------------- yh = y @ Wh + bh (G x C x C) ----------------
__global__ __launch_bounds__(256, 2)
void gemm_h_kernel(const float* __restrict__ Wh, const float* __restrict__ bh)
{
    constexpr int BM = 128, BN = 128, BK = 16;
    __shared__ float As[BK][BM];
    __shared__ float Bs[BK][BN];

    const int tid  = threadIdx.x;
    const int col0 = blockIdx.x * BN;
    const int row0 = blockIdx.y * BM;

    const int ty = tid >> 4, tx = tid & 15;
    const int trow = ty * 8, tcol = tx * 8;

    float acc[8][8];
#pragma unroll
    for (int i = 0; i < 8; i++)
#pragma unroll
        for (int j = 0; j < 8; j++) acc[i][j] = 0.f;

    for (int k0 = 0; k0 < C_DIM; k0 += BK) {
#pragma unroll
        for (int s = 0; s < 2; s++) {
            int l = tid + s * 256;
            int ar  = l >> 2;
            int akq = (l & 3) * 4;
            float4 av = *(const float4*)&g_y[(size_t)(row0 + ar) * C_DIM + k0 + akq];
            As[akq + 0][ar] = av.x;
            As[akq + 1][ar] = av.y;
            As[akq + 2][ar] = av.z;
            As[akq + 3][ar] = av.w;
            int bk  = l >> 5;
            int bcq = (l & 31) * 4;
            float4 bv = *(const float4*)&Wh[(size_t)(k0 + bk) * C_DIM + col0 + bcq];
            *(float4*)&Bs[bk][bcq] = bv;
        }
        __syncthreads();
#pragma unroll
        for (int k = 0; k < BK; k++) {
            float a[8], b[8];
#pragma unroll
            for (int i = 0; i < 8; i++) a[i] = As[k][trow + i];
#pragma unroll
            for (int j = 0; j < 8; j++) b[j] = Bs[k][tcol + j];
#pragma unroll
            for (int i = 0; i < 8; i++)
#pragma unroll
                for (int j = 0; j < 8; j++)
                    acc[i][j] = fmaf(a[i], b[j], acc[i][j]);
        }
        __syncthreads();
    }

    float bv[8];
#pragma unroll
    for (int j = 0; j < 8; j++) bv[j] = bh[col0 + tcol + j];
#pragma unroll
    for (int i = 0; i < 8; i++) {
        size_t off = (size_t)(row0 + trow + i) * C_DIM + col0 + tcol;
        float4 v0 = make_float4(acc[i][0] + bv[0], acc[i][1] + bv[1],
                                acc[i][2] + bv[2], acc[i][3] + bv[3]);
        float4 v1 = make_float4(acc[i][4] + bv[4], acc[i][5] + bv[5],
                                acc[i][6] + bv[6], acc[i][7] + bv[7]);
        *(float4*)&g_yh[off]     = v0;
        *(float4*)&g_yh[off + 4] = v1;
    }
}

// ---------------- out[n] = yh[ix[n]] ----------------
__global__ void gather_kernel(const int* __restrict__ ix, float* __restrict__ out) {
    size_t idx = (size_t)blockIdx.x * blockDim.x + threadIdx.x;  // over N*C/4
    int n  = (int)(idx >> 7);
    int cq = (int)(idx & 127) << 2;
    int g  = ix[n];
    *(float4*)&out[((size_t)n << 9) + cq] = *(const float4*)&g_yh[((size_t)g << 9) + cq];
}

extern "C" void kernel_launch(void* const* d_in, const int* in_sizes, int n_in,
                              void* d_out, int out_size) {
    const float* x  = (const float*)d_in[0];
    const int*   ix = (const int*)d_in[1];
    const float* Wf = (const float*)d_in[2];
    const float* bf = (const float*)d_in[3];
    const float* Wg = (const float*)d_in[4];
    const float* bg = (const float*)d_in[5];
    const float* Wh = (const float*)d_in[6];
    const float* bh = (const float*)d_in[7];
    float* out = (float*)d_out;

    zero_kernel<<<(G_DIM * C_DIM / 4) / 256, 256>>>();

    dim3 g1(8, N_ELEM / 128);
    fused_fg_kernel<<<g1, 256>>>(x, ix, Wf, bf, Wg, bg);

    agg_kernel<<<(N_ELEM * (C_DIM / 4)) / 256, 256>>>(ix);

    dim3 g2(C_DIM / 128, G_DIM / 128);
    gemm_h_kernel<<<g2, 256>>>(Wh, bh);

    gather_kernel<<<(N_ELEM * (C_DIM / 4)) / 256, 256>>>(ix, out);
}

// round 5
// speedup vs baseline: 1.3535x; 1.3535x over previous
#include <cuda_runtime.h>
#include <cuda_bf16.h>
#include <math.h>
#include <stdint.h>

#define N_ELEM 131072
#define C_DIM  512
#define G_DIM  4096
#define KTOT   1536     // 3 * C  (hi·Whi, hi·Wlo, lo·Whi blocks)
#define NOUT   1024     // Wf cols || Wg cols

// ---------------- scratch (device globals; no allocation allowed) ----------------
__device__ __nv_bfloat16 g_xhi[(size_t)N_ELEM * C_DIM];   // 128 MB
__device__ __nv_bfloat16 g_xlo[(size_t)N_ELEM * C_DIM];   // 128 MB
__device__ __nv_bfloat16 g_wcat[(size_t)NOUT * KTOT];     // 3 MB, K-major [n][k]
__device__ float g_fx[(size_t)N_ELEM * C_DIM];            // 256 MB
__device__ float g_eg[(size_t)N_ELEM * C_DIM];            // 256 MB
__device__ float g_denom[G_DIM * C_DIM];                  // 8 MB
__device__ float g_y[G_DIM * C_DIM];                      // 8 MB
__device__ float g_yh[G_DIM * C_DIM];                     // 8 MB

#define MMA16816(d, a0, a1, a2, a3, b0, b1) \
    asm volatile("mma.sync.aligned.m16n8k16.row.col.f32.bf16.bf16.f32 " \
                 "{%0,%1,%2,%3}, {%4,%5,%6,%7}, {%8,%9}, {%0,%1,%2,%3};" \
                 : "+f"((d)[0]), "+f"((d)[1]), "+f"((d)[2]), "+f"((d)[3]) \
                 : "r"(a0), "r"(a1), "r"(a2), "r"(a3), "r"(b0), "r"(b1))

// ---------------- zero accumulators ----------------
__global__ void zero_kernel() {
    int i = blockIdx.x * blockDim.x + threadIdx.x;   // G*C/4
    float4 z = make_float4(0.f, 0.f, 0.f, 0.f);
    ((float4*)g_denom)[i] = z;
    ((float4*)g_y)[i] = z;
}

// ---------------- split x into bf16 hi/lo ----------------
__global__ void convert_x_kernel(const float* __restrict__ x) {
    size_t idx = (size_t)blockIdx.x * blockDim.x + threadIdx.x;  // N*C/4
    float4 v = ((const float4*)x)[idx];
    __nv_bfloat16 h0 = __float2bfloat16(v.x);
    __nv_bfloat16 h1 = __float2bfloat16(v.y);
    __nv_bfloat16 h2 = __float2bfloat16(v.z);
    __nv_bfloat16 h3 = __float2bfloat16(v.w);
    __nv_bfloat162 ha; ha.x = h0; ha.y = h1;
    __nv_bfloat162 hb; hb.x = h2; hb.y = h3;
    ((__nv_bfloat162*)g_xhi)[2 * idx]     = ha;
    ((__nv_bfloat162*)g_xhi)[2 * idx + 1] = hb;
    __nv_bfloat162 la, lb;
    la.x = __float2bfloat16(v.x - __bfloat162float(h0));
    la.y = __float2bfloat16(v.y - __bfloat162float(h1));
    lb.x = __float2bfloat16(v.z - __bfloat162float(h2));
    lb.y = __float2bfloat16(v.w - __bfloat162float(h3));
    ((__nv_bfloat162*)g_xlo)[2 * idx]     = la;
    ((__nv_bfloat162*)g_xlo)[2 * idx + 1] = lb;
}

// ---------------- build Wcat [n=1024][k=1536] K-major bf16 ----------------
// k block 0: hi(W), block 1: lo(W), block 2: hi(W).  n<512 -> Wf, else Wg.
__global__ void build_wcat_kernel(const float* __restrict__ Wf,
                                  const float* __restrict__ Wg) {
    int i = blockIdx.x * blockDim.x + threadIdx.x;   // NOUT*KTOT
    int n = i / KTOT;
    int k = i - n * KTOT;
    int blk = k >> 9;
    int kk  = k & 511;
    const float* W = (n < 512) ? Wf : Wg;
    float w = W[(size_t)kk * C_DIM + (n & 511)];
    __nv_bfloat16 hi = __float2bfloat16(w);
    float v = (blk == 1) ? (w - __bfloat162float(hi)) : w;
    g_wcat[i] = __float2bfloat16(v);
}

// ---------------- mma.sync bf16 GEMM: [fx|eg] = A'[131072,1536] @ Wcat^T ----------
// Block tile 128(M) x 128(N), BK=32. 8 warps as 2(M) x 4(N), warp tile 64x32.
// Synchronous loads (register-staged double buffer), direct per-thread LDS
// fragment loads at the PTX-documented mma fragment coordinates.
// Smem pitch 40 bf16 (80B): fragment LDS word = 20*row + tig + 8*s,
// all 32 lanes distinct mod 32 -> conflict-free.
#define SPITCH 40

__global__ __launch_bounds__(256, 1)
void gemm_fg_mma(const int* __restrict__ ix,
                 const float* __restrict__ bf, const float* __restrict__ bg) {
    __shared__ __align__(16) __nv_bfloat16 smA[2][128][SPITCH];
    __shared__ __align__(16) __nv_bfloat16 smB[2][128][SPITCH];

    const int tid  = threadIdx.x;
    const int l    = tid & 31;
    const int warp = tid >> 5;
    const int bx   = blockIdx.x;          // 0..7 -> 128-col stripe of NOUT
    const int row0 = blockIdx.y * 128;
    const int n0g  = bx * 128;

    const int wm = warp >> 2;             // 0..1
    const int wn = warp & 3;              // 0..3
    const int m_base = wm * 64;
    const int n_base = wn * 32;
    const int gid = l >> 2, tig = l & 3;

    // staging: 512 uint4 chunks per tile (A and B each); 2 per thread
    const int m0l = tid >> 2,          c0l = tid & 3;           // rows 0..63
    const int m1l = (tid + 256) >> 2,  c1l = tid & 3;           // rows 64..127

    float acc[4][4][4];
#pragma unroll
    for (int t = 0; t < 4; t++)
#pragma unroll
        for (int n = 0; n < 4; n++)
#pragma unroll
            for (int r = 0; r < 4; r++) acc[t][n][r] = 0.f;

    uint4 aU0, aU1, bU0, bU1;

#define LOAD_REGS(ITER) do {                                                  \
        const int itv = (ITER);                                               \
        const __nv_bfloat16* asrc = (itv < 32) ? g_xhi : g_xlo;               \
        const int ksrc = (itv * 32) & 511;                                    \
        const int kb   = itv * 32;                                            \
        aU0 = *(const uint4*)(asrc + (size_t)(row0 + m0l) * C_DIM + ksrc + c0l * 8); \
        aU1 = *(const uint4*)(asrc + (size_t)(row0 + m1l) * C_DIM + ksrc + c1l * 8); \
        bU0 = *(const uint4*)(g_wcat + (size_t)(n0g + m0l) * KTOT + kb + c0l * 8);   \
        bU1 = *(const uint4*)(g_wcat + (size_t)(n0g + m1l) * KTOT + kb + c1l * 8);   \
    } while (0)

#define STORE_REGS(buf) do {                                                  \
        *(uint4*)&smA[buf][m0l][c0l * 8] = aU0;                               \
        *(uint4*)&smA[buf][m1l][c1l * 8] = aU1;                               \
        *(uint4*)&smB[buf][m0l][c0l * 8] = bU0;                               \
        *(uint4*)&smB[buf][m1l][c1l * 8] = bU1;                               \
    } while (0)

    LOAD_REGS(0);
    STORE_REGS(0);
    __syncthreads();

    const int NIT = KTOT / 32;   // 48
    for (int it = 0; it < NIT; it++) {
        const int cur = it & 1;
        if (it + 1 < NIT) LOAD_REGS(it + 1);

#pragma unroll
        for (int s = 0; s < 2; s++) {               // two k16 steps in BK=32
            const int k0 = s * 16 + 2 * tig;
            uint32_t aF[4][4];
#pragma unroll
            for (int t = 0; t < 4; t++) {
                const int r = m_base + t * 16 + gid;
                aF[t][0] = *(const uint32_t*)&smA[cur][r][k0];
                aF[t][1] = *(const uint32_t*)&smA[cur][r + 8][k0];
                aF[t][2] = *(const uint32_t*)&smA[cur][r][k0 + 8];
                aF[t][3] = *(const uint32_t*)&smA[cur][r + 8][k0 + 8];
            }
            uint32_t bF[4][2];
#pragma unroll
            for (int nt = 0; nt < 4; nt++) {
                const int rn = n_base + nt * 8 + gid;
                bF[nt][0] = *(const uint32_t*)&smB[cur][rn][k0];
                bF[nt][1] = *(const uint32_t*)&smB[cur][rn][k0 + 8];
            }
#pragma unroll
            for (int t = 0; t < 4; t++)
#pragma unroll
                for (int nt = 0; nt < 4; nt++)
                    MMA16816(acc[t][nt], aF[t][0], aF[t][1], aF[t][2], aF[t][3],
                             bF[nt][0], bF[nt][1]);
        }

        if (it + 1 < NIT) STORE_REGS(cur ^ 1);
        __syncthreads();
    }
#undef LOAD_REGS
#undef STORE_REGS

    // ---- epilogue ----
    const bool isG = (bx >= 4);
    const float* __restrict__ bias = isG ? bg : bf;

#pragma unroll
    for (int t = 0; t < 4; t++) {
#pragma unroll
        for (int h = 0; h < 2; h++) {
            const int m = row0 + m_base + t * 16 + gid + h * 8;
            int grp = 0;
            if (isG) grp = ix[m];
#pragma unroll
            for (int nt = 0; nt < 4; nt++) {
                const int cg = n0g + n_base + nt * 8 + 2 * tig;
                const int cw = cg & 511;
                float v0 = acc[t][nt][2 * h]     + bias[cw];
                float v1 = acc[t][nt][2 * h + 1] + bias[cw + 1];
                if (!isG) {
                    *(float2*)&g_fx[(size_t)m * C_DIM + cw] = make_float2(v0, v1);
                } else {
                    v0 = expf(v0);
                    v1 = expf(v1);
                    *(float2*)&g_eg[(size_t)m * C_DIM + cw] = make_float2(v0, v1);
                    float* dp = &g_denom[(size_t)grp * C_DIM + cw];
                    atomicAdd(dp,     v0);
                    atomicAdd(dp + 1, v1);
                }
            }
        }
    }
}

// ---------------- softmax-weighted aggregation: y[g] += fx * eg/denom[g] ----------------
__global__ void agg_kernel(const int* __restrict__ ix) {
    size_t idx = (size_t)blockIdx.x * blockDim.x + threadIdx.x;  // N*C/4
    int n  = (int)(idx >> 7);
    int cq = (int)(idx & 127) << 2;
    int g  = ix[n];
    size_t eoff = ((size_t)n << 9) + cq;
    size_t doff = ((size_t)g << 9) + cq;
    float4 e = *(const float4*)&g_eg[eoff];
    float4 f = *(const float4*)&g_fx[eoff];
    float4 d = *(const float4*)&g_denom[doff];
    float* yp = &g_y[doff];
    atomicAdd(yp + 0, f.x * (e.x / d.x));
    atomicAdd(yp + 1, f.y * (e.y / d.y));
    atomicAdd(yp + 2, f.z * (e.z / d.z));
    atomicAdd(yp + 3, f.w * (e.w / d.w));
}

// ---------------- yh = y @ Wh + bh (fp32 SIMT, small) ----------------
__global__ __launch_bounds__(256, 2)
void gemm_h_kernel(const float* __restrict__ Wh, const float* __restrict__ bh)
{
    constexpr int BM = 128, BN = 128, BK = 16;
    __shared__ float As[BK][BM];
    __shared__ float Bs[BK][BN];

    const int tid  = threadIdx.x;
    const int col0 = blockIdx.x * BN;
    const int row0 = blockIdx.y * BM;
    const int ty = tid >> 4, tx = tid & 15;
    const int trow = ty * 8, tcol = tx * 8;

    float acc[8][8];
#pragma unroll
    for (int i = 0; i < 8; i++)
#pragma unroll
        for (int j = 0; j < 8; j++) acc[i][j] = 0.f;

    for (int k0 = 0; k0 < C_DIM; k0 += BK) {
#pragma unroll
        for (int s = 0; s < 2; s++) {
            int ll = tid + s * 256;
            int ar  = ll >> 2;
            int akq = (ll & 3) * 4;
            float4 av = *(const float4*)&g_y[(size_t)(row0 + ar) * C_DIM + k0 + akq];
            As[akq + 0][ar] = av.x;
            As[akq + 1][ar] = av.y;
            As[akq + 2][ar] = av.z;
            As[akq + 3][ar] = av.w;
            int bk  = ll >> 5;
            int bcq = (ll & 31) * 4;
            float4 bv = *(const float4*)&Wh[(size_t)(k0 + bk) * C_DIM + col0 + bcq];
            *(float4*)&Bs[bk][bcq] = bv;
        }
        __syncthreads();
#pragma unroll
        for (int k = 0; k < BK; k++) {
            float a[8], b[8];
#pragma unroll
            for (int i = 0; i < 8; i++) a[i] = As[k][trow + i];
#pragma unroll
            for (int j = 0; j < 8; j++) b[j] = Bs[k][tcol + j];
#pragma unroll
            for (int i = 0; i < 8; i++)
#pragma unroll
                for (int j = 0; j < 8; j++)
                    acc[i][j] = fmaf(a[i], b[j], acc[i][j]);
        }
        __syncthreads();
    }

    float bv[8];
#pragma unroll
    for (int j = 0; j < 8; j++) bv[j] = bh[col0 + tcol + j];
#pragma unroll
    for (int i = 0; i < 8; i++) {
        size_t off = (size_t)(row0 + trow + i) * C_DIM + col0 + tcol;
        *(float4*)&g_yh[off]     = make_float4(acc[i][0] + bv[0], acc[i][1] + bv[1],
                                               acc[i][2] + bv[2], acc[i][3] + bv[3]);
        *(float4*)&g_yh[off + 4] = make_float4(acc[i][4] + bv[4], acc[i][5] + bv[5],
                                               acc[i][6] + bv[6], acc[i][7] + bv[7]);
    }
}

// ---------------- out[n] = yh[ix[n]] ----------------
__global__ void gather_kernel(const int* __restrict__ ix, float* __restrict__ out) {
    size_t idx = (size_t)blockIdx.x * blockDim.x + threadIdx.x;  // N*C/4
    int n  = (int)(idx >> 7);
    int cq = (int)(idx & 127) << 2;
    int g  = ix[n];
    *(float4*)&out[((size_t)n << 9) + cq] = *(const float4*)&g_yh[((size_t)g << 9) + cq];
}

extern "C" void kernel_launch(void* const* d_in, const int* in_sizes, int n_in,
                              void* d_out, int out_size) {
    const float* x  = (const float*)d_in[0];
    const int*   ix = (const int*)d_in[1];
    const float* Wf = (const float*)d_in[2];
    const float* bf = (const float*)d_in[3];
    const float* Wg = (const float*)d_in[4];
    const float* bg = (const float*)d_in[5];
    const float* Wh = (const float*)d_in[6];
    const float* bh = (const float*)d_in[7];
    float* out = (float*)d_out;

    zero_kernel<<<(G_DIM * C_DIM / 4) / 256, 256>>>();
    convert_x_kernel<<<(N_ELEM * (C_DIM / 4)) / 256, 256>>>(x);
    build_wcat_kernel<<<(NOUT * KTOT) / 256, 256>>>(Wf, Wg);

    dim3 g1(8, N_ELEM / 128);
    gemm_fg_mma<<<g1, 256>>>(ix, bf, bg);

    agg_kernel<<<(N_ELEM * (C_DIM / 4)) / 256, 256>>>(ix);

    dim3 g2(C_DIM / 128, G_DIM / 128);
    gemm_h_kernel<<<g2, 256>>>(Wh, bh);

    gather_kernel<<<(N_ELEM * (C_DIM / 4)) / 256, 256>>>(ix, out);
}

// round 6
// speedup vs baseline: 1.9943x; 1.4734x over previous
#include <cuda_runtime.h>
#include <cuda_bf16.h>
#include <math.h>
#include <stdint.h>

#define N_ELEM 131072
#define C_DIM  512
#define G_DIM  4096
#define NOUT   1024     // Wf cols || Wg cols

// ---------------- scratch (device globals; no allocation allowed) ----------------
__device__ __nv_bfloat16 g_whi[(size_t)NOUT * C_DIM];     // 1 MB, K-major [n][k]
__device__ __nv_bfloat16 g_wlo[(size_t)NOUT * C_DIM];     // 1 MB
__device__ float g_fx[(size_t)N_ELEM * C_DIM];            // 256 MB
__device__ float g_eg[(size_t)N_ELEM * C_DIM];            // 256 MB
__device__ float g_denom[G_DIM * C_DIM];                  // 8 MB
__device__ float g_y[G_DIM * C_DIM];                      // 8 MB
__device__ float g_yh[G_DIM * C_DIM];                     // 8 MB

#define MMA16816(d, a0, a1, a2, a3, b0, b1) \
    asm volatile("mma.sync.aligned.m16n8k16.row.col.f32.bf16.bf16.f32 " \
                 "{%0,%1,%2,%3}, {%4,%5,%6,%7}, {%8,%9}, {%0,%1,%2,%3};" \
                 : "+f"((d)[0]), "+f"((d)[1]), "+f"((d)[2]), "+f"((d)[3]) \
                 : "r"(a0), "r"(a1), "r"(a2), "r"(a3), "r"(b0), "r"(b1))

__device__ __forceinline__ uint32_t smem_u32(const void* p) {
    uint32_t a;
    asm("{ .reg .u64 t; cvta.to.shared.u64 t, %1; cvt.u32.u64 %0, t; }" : "=r"(a) : "l"(p));
    return a;
}
__device__ __forceinline__ void cp16(uint32_t saddr, const void* g) {
    asm volatile("cp.async.cg.shared.global [%0], [%1], 16;" :: "r"(saddr), "l"(g));
}

// ---------------- zero accumulators ----------------
__global__ void zero_kernel() {
    int i = blockIdx.x * blockDim.x + threadIdx.x;   // G*C/4
    float4 z = make_float4(0.f, 0.f, 0.f, 0.f);
    ((float4*)g_denom)[i] = z;
    ((float4*)g_y)[i] = z;
}

// ---------------- build Whi/Wlo [n=1024][k=512] K-major bf16 ----------------
__global__ void build_w_kernel(const float* __restrict__ Wf,
                               const float* __restrict__ Wg) {
    int i = blockIdx.x * blockDim.x + threadIdx.x;   // NOUT*C_DIM
    int n = i >> 9;
    int k = i & 511;
    const float* W = (n < 512) ? Wf : Wg;
    float w = W[(size_t)k * C_DIM + (n & 511)];
    __nv_bfloat16 hi = __float2bfloat16(w);
    g_whi[i] = hi;
    g_wlo[i] = __float2bfloat16(w - __bfloat162float(hi));
}

// ---------------- mma.sync bf16-split GEMM: [fx|eg] = x @ [Wf|Wg] --------------
// A (x fp32) read once per CTA k-chunk, split hi/lo in regs. Per chunk, 3 MMA
// passes: hi*Whi + hi*Wlo + lo*Whi (lo*lo dropped, ~2^-18 rel).
// Block tile 128(M) x 128(N), BK=32, 16 chunks. 8 warps as 2(M) x 4(N).
// Smem pitch 40 bf16 (80B): fragment LDS conflict-free (verified R5).
#define SPITCH 40
#define TILE_E (128 * SPITCH)        // bf16 elems per tile (10240 B)
#define STG_E  (4 * TILE_E)          // elems per stage (4 tiles)

__global__ __launch_bounds__(256, 1)
void gemm_fg_mma(const float* __restrict__ x, const int* __restrict__ ix,
                 const float* __restrict__ bf, const float* __restrict__ bg) {
    extern __shared__ __nv_bfloat16 sm[];
    // stage s: [AHI, ALO, BHI, BLO], each 128 x SPITCH

    const int tid  = threadIdx.x;
    const int l    = tid & 31;
    const int warp = tid >> 5;
    const int bx   = blockIdx.x;          // 0..7 -> 128-col stripe of NOUT
    const int row0 = blockIdx.y * 128;
    const int n0g  = bx * 128;

    const int wm = warp >> 2;             // 0..1
    const int wn = warp & 3;              // 0..3
    const int m_base = wm * 64;
    const int n_base = wn * 32;
    const int gid = l >> 2, tig = l & 3;

    float acc[4][4][4];
#pragma unroll
    for (int t = 0; t < 4; t++)
#pragma unroll
        for (int n = 0; n < 4; n++)
#pragma unroll
            for (int r = 0; r < 4; r++) acc[t][n][r] = 0.f;

    // A staging: 1024 float4 units/tile (128 rows x 8 segs), 4 per thread
    float4 stg[4];

#define LOAD_A(CH) do {                                                       \
        const int kc_ = (CH) * 32;                                            \
        _Pragma("unroll")                                                     \
        for (int i_ = 0; i_ < 4; i_++) {                                      \
            int u_ = tid + i_ * 256;                                          \
            int r_ = u_ >> 3, s_ = u_ & 7;                                    \
            stg[i_] = *(const float4*)(x + (size_t)(row0 + r_) * C_DIM + kc_ + s_ * 4); \
        }                                                                     \
    } while (0)

#define STORE_A(BUF) do {                                                     \
        __nv_bfloat16* ahi_ = sm + (BUF) * STG_E;                             \
        __nv_bfloat16* alo_ = ahi_ + TILE_E;                                  \
        _Pragma("unroll")                                                     \
        for (int i_ = 0; i_ < 4; i_++) {                                      \
            int u_ = tid + i_ * 256;                                          \
            int r_ = u_ >> 3, s_ = u_ & 7;                                    \
            float4 v_ = stg[i_];                                              \
            __nv_bfloat162 h01_, h23_, l01_, l23_;                            \
            h01_.x = __float2bfloat16(v_.x); h01_.y = __float2bfloat16(v_.y); \
            h23_.x = __float2bfloat16(v_.z); h23_.y = __float2bfloat16(v_.w); \
            l01_.x = __float2bfloat16(v_.x - __bfloat162float(h01_.x));       \
            l01_.y = __float2bfloat16(v_.y - __bfloat162float(h01_.y));       \
            l23_.x = __float2bfloat16(v_.z - __bfloat162float(h23_.x));       \
            l23_.y = __float2bfloat16(v_.w - __bfloat162float(h23_.y));       \
            uint2 H_, L_;                                                     \
            H_.x = *(uint32_t*)&h01_; H_.y = *(uint32_t*)&h23_;               \
            L_.x = *(uint32_t*)&l01_; L_.y = *(uint32_t*)&l23_;               \
            *(uint2*)(ahi_ + r_ * SPITCH + s_ * 4) = H_;                      \
            *(uint2*)(alo_ + r_ * SPITCH + s_ * 4) = L_;                      \
        }                                                                     \
    } while (0)

#define LOAD_B(BUF, CH) do {                                                  \
        const int kc_ = (CH) * 32;                                            \
        uint32_t bhi_ = smem_u32(sm + (BUF) * STG_E + 2 * TILE_E);            \
        uint32_t blo_ = bhi_ + TILE_E * 2;                                    \
        _Pragma("unroll")                                                     \
        for (int i_ = 0; i_ < 2; i_++) {                                      \
            int u_ = tid + i_ * 256;                                          \
            int nr_ = u_ >> 2, ch_ = u_ & 3;                                  \
            size_t go_ = (size_t)(n0g + nr_) * C_DIM + kc_ + ch_ * 8;         \
            uint32_t so_ = nr_ * (SPITCH * 2) + ch_ * 16;                     \
            cp16(bhi_ + so_, g_whi + go_);                                    \
            cp16(blo_ + so_, g_wlo + go_);                                    \
        }                                                                     \
        asm volatile("cp.async.commit_group;" ::: "memory");                  \
    } while (0)

    // prologue: chunk 0 into buf 0
    LOAD_B(0, 0);
    LOAD_A(0);
    STORE_A(0);
    asm volatile("cp.async.wait_group 0;" ::: "memory");
    __syncthreads();

    for (int it = 0; it < 16; it++) {
        const int cur = it & 1;
        if (it + 1 < 16) {
            LOAD_B(cur ^ 1, it + 1);
            LOAD_A(it + 1);
        }

        const __nv_bfloat16* Ahi = sm + cur * STG_E;
        const __nv_bfloat16* Alo = Ahi + TILE_E;
        const __nv_bfloat16* Bhi = Ahi + 2 * TILE_E;
        const __nv_bfloat16* Blo = Ahi + 3 * TILE_E;

#pragma unroll
        for (int s = 0; s < 2; s++) {
            const int k0 = s * 16 + 2 * tig;
            uint32_t aH[4][4], aL[4][4];
#pragma unroll
            for (int t = 0; t < 4; t++) {
                const int r = m_base + t * 16 + gid;
                aH[t][0] = *(const uint32_t*)(Ahi + r * SPITCH + k0);
                aH[t][1] = *(const uint32_t*)(Ahi + (r + 8) * SPITCH + k0);
                aH[t][2] = *(const uint32_t*)(Ahi + r * SPITCH + k0 + 8);
                aH[t][3] = *(const uint32_t*)(Ahi + (r + 8) * SPITCH + k0 + 8);
                aL[t][0] = *(const uint32_t*)(Alo + r * SPITCH + k0);
                aL[t][1] = *(const uint32_t*)(Alo + (r + 8) * SPITCH + k0);
                aL[t][2] = *(const uint32_t*)(Alo + r * SPITCH + k0 + 8);
                aL[t][3] = *(const uint32_t*)(Alo + (r + 8) * SPITCH + k0 + 8);
            }
            uint32_t bH[4][2], bL[4][2];
#pragma unroll
            for (int nt = 0; nt < 4; nt++) {
                const int rn = n_base + nt * 8 + gid;
                bH[nt][0] = *(const uint32_t*)(Bhi + rn * SPITCH + k0);
                bH[nt][1] = *(const uint32_t*)(Bhi + rn * SPITCH + k0 + 8);
                bL[nt][0] = *(const uint32_t*)(Blo + rn * SPITCH + k0);
                bL[nt][1] = *(const uint32_t*)(Blo + rn * SPITCH + k0 + 8);
            }
#pragma unroll
            for (int t = 0; t < 4; t++)
#pragma unroll
                for (int nt = 0; nt < 4; nt++) {
                    MMA16816(acc[t][nt], aH[t][0], aH[t][1], aH[t][2], aH[t][3],
                             bH[nt][0], bH[nt][1]);
                    MMA16816(acc[t][nt], aH[t][0], aH[t][1], aH[t][2], aH[t][3],
                             bL[nt][0], bL[nt][1]);
                    MMA16816(acc[t][nt], aL[t][0], aL[t][1], aL[t][2], aL[t][3],
                             bH[nt][0], bH[nt][1]);
                }
        }

        if (it + 1 < 16) {
            STORE_A(cur ^ 1);
            asm volatile("cp.async.wait_group 0;" ::: "memory");
        }
        __syncthreads();
    }
#undef LOAD_A
#undef STORE_A
#undef LOAD_B

    // ---- epilogue (identical to verified R5) ----
    const bool isG = (bx >= 4);
    const float* __restrict__ bias = isG ? bg : bf;

#pragma unroll
    for (int t = 0; t < 4; t++) {
#pragma unroll
        for (int h = 0; h < 2; h++) {
            const int m = row0 + m_base + t * 16 + gid + h * 8;
            int grp = 0;
            if (isG) grp = ix[m];
#pragma unroll
            for (int nt = 0; nt < 4; nt++) {
                const int cg = n0g + n_base + nt * 8 + 2 * tig;
                const int cw = cg & 511;
                float v0 = acc[t][nt][2 * h]     + bias[cw];
                float v1 = acc[t][nt][2 * h + 1] + bias[cw + 1];
                if (!isG) {
                    *(float2*)&g_fx[(size_t)m * C_DIM + cw] = make_float2(v0, v1);
                } else {
                    v0 = expf(v0);
                    v1 = expf(v1);
                    *(float2*)&g_eg[(size_t)m * C_DIM + cw] = make_float2(v0, v1);
                    float* dp = &g_denom[(size_t)grp * C_DIM + cw];
                    atomicAdd(dp,     v0);
                    atomicAdd(dp + 1, v1);
                }
            }
        }
    }
}

// ---------------- softmax-weighted aggregation: y[g] += fx * eg/denom[g] ----------------
__global__ void agg_kernel(const int* __restrict__ ix) {
    size_t idx = (size_t)blockIdx.x * blockDim.x + threadIdx.x;  // N*C/4
    int n  = (int)(idx >> 7);
    int cq = (int)(idx & 127) << 2;
    int g  = ix[n];
    size_t eoff = ((size_t)n << 9) + cq;
    size_t doff = ((size_t)g << 9) + cq;
    float4 e = *(const float4*)&g_eg[eoff];
    float4 f = *(const float4*)&g_fx[eoff];
    float4 d = *(const float4*)&g_denom[doff];
    float* yp = &g_y[doff];
    atomicAdd(yp + 0, f.x * (e.x / d.x));
    atomicAdd(yp + 1, f.y * (e.y / d.y));
    atomicAdd(yp + 2, f.z * (e.z / d.z));
    atomicAdd(yp + 3, f.w * (e.w / d.w));
}

// ---------------- yh = y @ Wh + bh (fp32 SIMT, small) ----------------
__global__ __launch_bounds__(256, 2)
void gemm_h_kernel(const float* __restrict__ Wh, const float* __restrict__ bh)
{
    constexpr int BM = 128, BN = 128, BK = 16;
    __shared__ float As[BK][BM];
    __shared__ float Bs[BK][BN];

    const int tid  = threadIdx.x;
    const int col0 = blockIdx.x * BN;
    const int row0 = blockIdx.y * BM;
    const int ty = tid >> 4, tx = tid & 15;
    const int trow = ty * 8, tcol = tx * 8;

    float acc[8][8];
#pragma unroll
    for (int i = 0; i < 8; i++)
#pragma unroll
        for (int j = 0; j < 8; j++) acc[i][j] = 0.f;

    for (int k0 = 0; k0 < C_DIM; k0 += BK) {
#pragma unroll
        for (int s = 0; s < 2; s++) {
            int ll = tid + s * 256;
            int ar  = ll >> 2;
            int akq = (ll & 3) * 4;
            float4 av = *(const float4*)&g_y[(size_t)(row0 + ar) * C_DIM + k0 + akq];
            As[akq + 0][ar] = av.x;
            As[akq + 1][ar] = av.y;
            As[akq + 2][ar] = av.z;
            As[akq + 3][ar] = av.w;
            int bk  = ll >> 5;
            int bcq = (ll & 31) * 4;
            float4 bv = *(const float4*)&Wh[(size_t)(k0 + bk) * C_DIM + col0 + bcq];
            *(float4*)&Bs[bk][bcq] = bv;
        }
        __syncthreads();
#pragma unroll
        for (int k = 0; k < BK; k++) {
            float a[8], b[8];
#pragma unroll
            for (int i = 0; i < 8; i++) a[i] = As[k][trow + i];
#pragma unroll
            for (int j = 0; j < 8; j++) b[j] = Bs[k][tcol + j];
#pragma unroll
            for (int i = 0; i < 8; i++)
#pragma unroll
                for (int j = 0; j < 8; j++)
                    acc[i][j] = fmaf(a[i], b[j], acc[i][j]);
        }
        __syncthreads();
    }

    float bv[8];
#pragma unroll
    for (int j = 0; j < 8; j++) bv[j] = bh[col0 + tcol + j];
#pragma unroll
    for (int i = 0; i < 8; i++) {
        size_t off = (size_t)(row0 + trow + i) * C_DIM + col0 + tcol;
        *(float4*)&g_yh[off]     = make_float4(acc[i][0] + bv[0], acc[i][1] + bv[1],
                                               acc[i][2] + bv[2], acc[i][3] + bv[3]);
        *(float4*)&g_yh[off + 4] = make_float4(acc[i][4] + bv[4], acc[i][5] + bv[5],
                                               acc[i][6] + bv[6], acc[i][7] + bv[7]);
    }
}

// ---------------- out[n] = yh[ix[n]] ----------------
__global__ void gather_kernel(const int* __restrict__ ix, float* __restrict__ out) {
    size_t idx = (size_t)blockIdx.x * blockDim.x + threadIdx.x;  // N*C/4
    int n  = (int)(idx >> 7);
    int cq = (int)(idx & 127) << 2;
    int g  = ix[n];
    *(float4*)&out[((size_t)n << 9) + cq] = *(const float4*)&g_yh[((size_t)g << 9) + cq];
}

extern "C" void kernel_launch(void* const* d_in, const int* in_sizes, int n_in,
                              void* d_out, int out_size) {
    const float* x  = (const float*)d_in[0];
    const int*   ix = (const int*)d_in[1];
    const float* Wf = (const float*)d_in[2];
    const float* bf = (const float*)d_in[3];
    const float* Wg = (const float*)d_in[4];
    const float* bg = (const float*)d_in[5];
    const float* Wh = (const float*)d_in[6];
    const float* bh = (const float*)d_in[7];
    float* out = (float*)d_out;

    const int SMEM = 2 * 4 * TILE_E * 2;   // 81920 bytes
    cudaFuncSetAttribute(gemm_fg_mma, cudaFuncAttributeMaxDynamicSharedMemorySize, SMEM);

    zero_kernel<<<(G_DIM * C_DIM / 4) / 256, 256>>>();
    build_w_kernel<<<(NOUT * C_DIM) / 256, 256>>>(Wf, Wg);

    dim3 g1(8, N_ELEM / 128);
    gemm_fg_mma<<<g1, 256, SMEM>>>(x, ix, bf, bg);

    agg_kernel<<<(N_ELEM * (C_DIM / 4)) / 256, 256>>>(ix);

    dim3 g2(C_DIM / 128, G_DIM / 128);
    gemm_h_kernel<<<g2, 256>>>(Wh, bh);

    gather_kernel<<<(N_ELEM * (C_DIM / 4)) / 256, 256>>>(ix, out);
}